// round 1
// baseline (speedup 1.0000x reference)
#include <cuda_runtime.h>
#include <math.h>

#define B_  4
#define N_  4096
#define D_  64
#define TM  128
#define TN  128
#define LDSS 132   // padded smem stride (floats), keeps 16B alignment

// FMA-only exp: exp(x) = 2^(x*log2e), range-reduce, deg-6 Taylor for 2^f,
// exponent via integer stuffing. Avoids MUFU (rt=8/SMSP would bottleneck).
__device__ __forceinline__ float fast_exp(float x) {
    x = fmaxf(x, -87.0f);                      // keep exponent stuffing legal
    float y = x * 1.4426950408889634f;
    float t = y + 12582912.0f;                 // round-to-nearest integer
    int   e = __float_as_int(t) - 0x4B400000;  // integer part
    float n = t - 12582912.0f;
    float f = y - n;                           // f in [-0.5, 0.5]
    float p = 1.5403530e-4f;
    p = fmaf(p, f, 1.3333558e-3f);
    p = fmaf(p, f, 9.6181291e-3f);
    p = fmaf(p, f, 5.5504109e-2f);
    p = fmaf(p, f, 2.4022651e-1f);
    p = fmaf(p, f, 6.9314718e-1f);
    p = fmaf(p, f, 1.0f);
    return p * __int_as_float((e + 127) << 23);
}

__global__ __launch_bounds__(256, 1)
void graphconstruct_kernel(const float* __restrict__ X, float* __restrict__ out) {
    extern __shared__ float smem[];
    float* As     = smem;                       // [64][132] transposed A tile
    float* Bs     = smem + D_ * LDSS;           // [64][132] transposed B tile
    float* c_s    = Bs   + D_ * LDSS;           // [128] row self-dot (softmax shift)
    float* zinv_s = c_s  + TM;                  // [128] 1/rowsum

    const int tid = threadIdx.x;
    const int tx  = tid & 15;                   // 16 thread-cols
    const int ty  = tid >> 4;                   // 16 thread-rows
    const int b   = blockIdx.x >> 5;            // 32 row-blocks per batch
    const int r0  = (blockIdx.x & 31) * TM;

    const float* Xb = X + (size_t)b * N_ * D_;

    // ---- Load A strip (TM x D) transposed into As[k][row] ----
    #pragma unroll
    for (int i = 0; i < 8; i++) {
        int v  = tid + i * 256;                 // 2048 float4 total
        int m  = v >> 4;
        int d4 = (v & 15) << 2;
        float4 val = *(const float4*)(Xb + (size_t)(r0 + m) * D_ + d4);
        As[(d4 + 0) * LDSS + m] = val.x;
        As[(d4 + 1) * LDSS + m] = val.y;
        As[(d4 + 2) * LDSS + m] = val.z;
        As[(d4 + 3) * LDSS + m] = val.w;
    }
    __syncthreads();

    // ---- c_n = ||x_n||^2 : provably >= within ~31.4 of the row max ----
    if (tid < TM) {
        float c = 0.f;
        #pragma unroll
        for (int k = 0; k < D_; k++) {
            float a = As[k * LDSS + tid];
            c = fmaf(a, a, c);
        }
        c_s[tid] = c;
    }

    float rowsum[8];
    #pragma unroll
    for (int i = 0; i < 8; i++) rowsum[i] = 0.f;

    for (int t = 0; t < N_ / TN; t++) {
        const int m0 = t * TN;
        __syncthreads();                         // Bs consumers from prev tile done
        #pragma unroll
        for (int i = 0; i < 8; i++) {
            int v  = tid + i * 256;
            int m  = v >> 4;
            int d4 = (v & 15) << 2;
            float4 val = *(const float4*)(Xb + (size_t)(m0 + m) * D_ + d4);
            Bs[(d4 + 0) * LDSS + m] = val.x;
            Bs[(d4 + 1) * LDSS + m] = val.y;
            Bs[(d4 + 2) * LDSS + m] = val.z;
            Bs[(d4 + 3) * LDSS + m] = val.w;
        }
        __syncthreads();

        float acc[8][8];
        #pragma unroll
        for (int i = 0; i < 8; i++)
            #pragma unroll
            for (int j = 0; j < 8; j++) acc[i][j] = 0.f;

        #pragma unroll 8
        for (int k = 0; k < D_; k++) {
            float4 a0 = *(const float4*)&As[k * LDSS + ty * 8];
            float4 a1 = *(const float4*)&As[k * LDSS + ty * 8 + 4];
            float4 b0 = *(const float4*)&Bs[k * LDSS + tx * 8];
            float4 b1 = *(const float4*)&Bs[k * LDSS + tx * 8 + 4];
            float av[8] = {a0.x, a0.y, a0.z, a0.w, a1.x, a1.y, a1.z, a1.w};
            float bv[8] = {b0.x, b0.y, b0.z, b0.w, b1.x, b1.y, b1.z, b1.w};
            #pragma unroll
            for (int i = 0; i < 8; i++)
                #pragma unroll
                for (int j = 0; j < 8; j++)
                    acc[i][j] = fmaf(av[i], bv[j], acc[i][j]);
        }

        // exp(s - c_row), accumulate row sums, stream out unnormalized values
        #pragma unroll
        for (int i = 0; i < 8; i++) {
            int row = ty * 8 + i;
            float c = c_s[row];
            float e0 = fast_exp(acc[i][0] - c);
            float e1 = fast_exp(acc[i][1] - c);
            float e2 = fast_exp(acc[i][2] - c);
            float e3 = fast_exp(acc[i][3] - c);
            float e4 = fast_exp(acc[i][4] - c);
            float e5 = fast_exp(acc[i][5] - c);
            float e6 = fast_exp(acc[i][6] - c);
            float e7 = fast_exp(acc[i][7] - c);
            rowsum[i] += ((e0 + e1) + (e2 + e3)) + ((e4 + e5) + (e6 + e7));
            float* orow = out + ((size_t)(b * N_ + r0 + row)) * N_ + m0 + tx * 8;
            float4 w0 = make_float4(e0, e1, e2, e3);
            float4 w1 = make_float4(e4, e5, e6, e7);
            *(float4*)orow       = w0;
            *(float4*)(orow + 4) = w1;
        }
    }

    // ---- reduce rowsum across the 16 tx threads (16-lane shfl tree) ----
    #pragma unroll
    for (int i = 0; i < 8; i++) {
        float s = rowsum[i];
        s += __shfl_xor_sync(0xffffffffu, s, 1);
        s += __shfl_xor_sync(0xffffffffu, s, 2);
        s += __shfl_xor_sync(0xffffffffu, s, 4);
        s += __shfl_xor_sync(0xffffffffu, s, 8);
        if (tx == 0) zinv_s[ty * 8 + i] = 1.0f / s;
    }
    __syncthreads();   // also fences the global writes within the block

    // ---- in-place scale pass (rows just written -> mostly L2 hits) ----
    for (int r = 0; r < TM; r++) {
        float zi = zinv_s[r];
        float4* row = (float4*)(out + ((size_t)(b * N_ + r0 + r)) * N_);
        #pragma unroll 4
        for (int c4 = tid; c4 < N_ / 4; c4 += 256) {
            float4 v = row[c4];
            v.x *= zi; v.y *= zi; v.z *= zi; v.w *= zi;
            row[c4] = v;
        }
    }
}

extern "C" void kernel_launch(void* const* d_in, const int* in_sizes, int n_in,
                              void* d_out, int out_size) {
    const float* X = (const float*)d_in[0];
    float* out = (float*)d_out;
    const int smem_bytes = (2 * D_ * LDSS + 2 * TM) * (int)sizeof(float); // 68608
    cudaFuncSetAttribute(graphconstruct_kernel,
                         cudaFuncAttributeMaxDynamicSharedMemorySize, smem_bytes);
    graphconstruct_kernel<<<B_ * (N_ / TM), 256, smem_bytes>>>(X, out);
}

// round 4
// speedup vs baseline: 1.7144x; 1.7144x over previous
#include <cuda_runtime.h>
#include <cuda_bf16.h>
#include <cstdint>

#define B_  4
#define N_  4096
#define D_  64
#define TM  128
#define TN  128
#define NTILES (N_ / TN)

// smem layout (byte offsets). Row stride 272B (136 bf16) -> conflict-free ldmatrix.
#define LDST    272
#define A_OFF   0                       // 128 x (hi64|lo64) bf16 = 128*272
#define B0_OFF  (128 * LDST)
#define B1_OFF  (2 * 128 * LDST)
#define CS_OFF  (3 * 128 * LDST)        // c_s[128] f32
#define RS_OFF  (CS_OFF + 512)          // rsum[2][128] f32
#define ZI_OFF  (RS_OFF + 1024)         // zinv[128] f32
#define SMEM_BYTES (ZI_OFF + 512)

typedef unsigned long long u64_t;

// ---------------- packed f32x2 helpers ----------------
static __device__ __forceinline__ u64_t pkf(float a, float b) {
    u64_t r; asm("mov.b64 %0,{%1,%2};" : "=l"(r) : "f"(a), "f"(b)); return r;
}
static __device__ __forceinline__ u64_t pku(uint32_t a, uint32_t b) {
    u64_t r; asm("mov.b64 %0,{%1,%2};" : "=l"(r) : "r"(a), "r"(b)); return r;
}
static __device__ __forceinline__ void upku(u64_t v, uint32_t& a, uint32_t& b) {
    asm("mov.b64 {%0,%1},%2;" : "=r"(a), "=r"(b) : "l"(v));
}
static __device__ __forceinline__ void upkf(u64_t v, float& a, float& b) {
    asm("mov.b64 {%0,%1},%2;" : "=f"(a), "=f"(b) : "l"(v));
}
static __device__ __forceinline__ u64_t f2fma(u64_t a, u64_t b, u64_t c) {
    u64_t d; asm("fma.rn.f32x2 %0,%1,%2,%3;" : "=l"(d) : "l"(a), "l"(b), "l"(c)); return d;
}
static __device__ __forceinline__ u64_t f2add(u64_t a, u64_t b) {
    u64_t d; asm("add.rn.f32x2 %0,%1,%2;" : "=l"(d) : "l"(a), "l"(b)); return d;
}
static __device__ __forceinline__ u64_t f2mul(u64_t a, u64_t b) {
    u64_t d; asm("mul.rn.f32x2 %0,%1,%2;" : "=l"(d) : "l"(a), "l"(b)); return d;
}

struct ExpC {
    u64_t L2E2, BIG2, NBIG2, MONE2, C4, C3, C2, C1, ONE2;
};

// packed exp(s - c): negcl2 = {-c*log2e, -c*log2e}; clampv = c - 80
static __device__ __forceinline__ u64_t exp_pair(float sa0, float sb0, u64_t negcl2,
                                                 float clampv, const ExpC& K) {
    float sa = fmaxf(sa0, clampv);
    float sb = fmaxf(sb0, clampv);
    u64_t y2 = f2fma(pkf(sa, sb), K.L2E2, negcl2);
    u64_t t2 = f2add(y2, K.BIG2);
    u64_t n2 = f2add(t2, K.NBIG2);
    u64_t f2_ = f2fma(n2, K.MONE2, y2);
    u64_t p2 = f2fma(K.C4, f2_, K.C3);
    p2 = f2fma(p2, f2_, K.C2);
    p2 = f2fma(p2, f2_, K.C1);
    p2 = f2fma(p2, f2_, K.ONE2);
    uint32_t tl, th; upku(t2, tl, th);
    const uint32_t EC = 0x0000007Fu - 0x4B400000u;
    return f2mul(p2, pku((tl + EC) << 23, (th + EC) << 23));
}

// ---------------- mma / ldmatrix wrappers ----------------
static __device__ __forceinline__ void ldsm_x4(uint32_t addr, uint32_t r[4]) {
    asm volatile("ldmatrix.sync.aligned.m8n8.x4.shared.b16 {%0,%1,%2,%3}, [%4];"
                 : "=r"(r[0]), "=r"(r[1]), "=r"(r[2]), "=r"(r[3]) : "r"(addr));
}
static __device__ __forceinline__ void mma16816(float d[4], const uint32_t a[4],
                                                uint32_t b0, uint32_t b1) {
    asm volatile("mma.sync.aligned.m16n8k16.row.col.f32.bf16.bf16.f32 "
                 "{%0,%1,%2,%3}, {%4,%5,%6,%7}, {%8,%9}, {%0,%1,%2,%3};"
                 : "+f"(d[0]), "+f"(d[1]), "+f"(d[2]), "+f"(d[3])
                 : "r"(a[0]), "r"(a[1]), "r"(a[2]), "r"(a[3]), "r"(b0), "r"(b1));
}

// ---------------- fp32 -> (hi,lo) bf16 padded smem store ----------------
static __device__ __forceinline__ uint32_t packbf2(__nv_bfloat16 a, __nv_bfloat16 b) {
    union { __nv_bfloat162 v; uint32_t u; } cv;
    cv.v = __halves2bfloat162(a, b);
    return cv.u;
}
static __device__ __forceinline__ void store_hilo(char* tile, int row, int k4, float4 v) {
    char* p = tile + row * LDST + k4 * 2;
    __nv_bfloat16 h0 = __float2bfloat16(v.x), h1 = __float2bfloat16(v.y);
    __nv_bfloat16 h2 = __float2bfloat16(v.z), h3 = __float2bfloat16(v.w);
    float l0 = v.x - __bfloat162float(h0), l1 = v.y - __bfloat162float(h1);
    float l2 = v.z - __bfloat162float(h2), l3 = v.w - __bfloat162float(h3);
    uint2 hp, lp;
    hp.x = packbf2(h0, h1); hp.y = packbf2(h2, h3);
    lp.x = packbf2(__float2bfloat16(l0), __float2bfloat16(l1));
    lp.y = packbf2(__float2bfloat16(l2), __float2bfloat16(l3));
    *(uint2*)p         = hp;    // hi at cols [0,64)
    *(uint2*)(p + 128) = lp;    // lo at cols [64,128)
}

// K-step -> element offset inside (hi|lo) 128-col row.
// A_cat = [hi | lo | hi], B_cat = [hi | hi | lo]  => s = hi.hi + lo.hi + hi.lo
__device__ __constant__ int A_KOFF[12] = {0,16,32,48, 64,80,96,112, 0,16,32,48};
__device__ __constant__ int B_KOFF[12] = {0,16,32,48, 0,16,32,48, 64,80,96,112};

__global__ __launch_bounds__(256, 1)
void graphconstruct_mma_kernel(const float* __restrict__ X, float* __restrict__ out) {
    extern __shared__ __align__(16) char sm[];
    const uint32_t sbase = (uint32_t)__cvta_generic_to_shared(sm);

    const int tid = threadIdx.x;
    const int wid = tid >> 5;
    const int lane = tid & 31;
    const int b  = blockIdx.x >> 5;
    const int r0 = (blockIdx.x & 31) * TM;
    const float* Xb = X + (size_t)b * N_ * D_;

    float* c_s  = (float*)(sm + CS_OFF);
    float* rsum = (float*)(sm + RS_OFF);
    float* zinv = (float*)(sm + ZI_OFF);

    // ---- load A strip (128 x 64 f32) -> hi/lo bf16 ----
    #pragma unroll
    for (int i = 0; i < 8; i++) {
        int v = tid + i * 256;
        int row = v >> 4, k4 = (v & 15) << 2;
        float4 val = *(const float4*)(Xb + (size_t)(r0 + row) * D_ + k4);
        store_hilo(sm + A_OFF, row, k4, val);
    }
    // ---- c_n = ||x_n||^2 fp32 ----
    if (tid < TM) {
        float c = 0.f;
        const float* rp = Xb + (size_t)(r0 + tid) * D_;
        #pragma unroll
        for (int k4 = 0; k4 < 16; k4++) {
            float4 v = *(const float4*)(rp + k4 * 4);
            c = fmaf(v.x, v.x, c); c = fmaf(v.y, v.y, c);
            c = fmaf(v.z, v.z, c); c = fmaf(v.w, v.w, c);
        }
        c_s[tid] = c;
    }
    // ---- B tile 0 ----
    #pragma unroll
    for (int i = 0; i < 8; i++) {
        int v = tid + i * 256;
        int row = v >> 4, k4 = (v & 15) << 2;
        float4 val = *(const float4*)(Xb + (size_t)row * D_ + k4);
        store_hilo(sm + B0_OFF, row, k4, val);
    }
    __syncthreads();

    // ---- per-warp geometry ----
    const int mblk = (wid & 3) * 32;        // M block of warp (32 rows)
    const int nhalf = wid >> 2;             // 0/1 -> N cols [0,64)/[64,128)
    const int nblk = nhalf * 64;
    const int g8  = lane >> 3;              // ldmatrix group
    const int rowoff = (g8 & 1) * 8 + (lane & 7);
    const int kch8   = (g8 >> 1) * 8;       // 0 or 8 within k16
    const int g4  = lane >> 2;              // acc row group
    const int col2 = (lane & 3) * 2;        // acc col pair

    const uint32_t a_base0 = sbase + A_OFF + (uint32_t)(mblk + rowoff) * LDST + kch8 * 2;
    const uint32_t a_base1 = a_base0 + 16u * LDST;

    // ---- epilogue constants ----
    const float L2E = 1.4426950408889634f;
    ExpC K;
    K.L2E2 = pkf(L2E, L2E);
    K.BIG2 = pkf(12582912.0f, 12582912.0f);  K.NBIG2 = pkf(-12582912.0f, -12582912.0f);
    K.MONE2 = pkf(-1.0f, -1.0f);             K.ONE2 = pkf(1.0f, 1.0f);
    K.C4 = pkf(9.6181291e-3f, 9.6181291e-3f);
    K.C3 = pkf(5.5504109e-2f, 5.5504109e-2f);
    K.C2 = pkf(2.4022651e-1f, 2.4022651e-1f);
    K.C1 = pkf(6.9314718e-1f, 6.9314718e-1f);

    float cA[2], cB[2];
    u64_t negA[2], negB[2];
    float clA[2], clB[2];
    #pragma unroll
    for (int mt = 0; mt < 2; mt++) {
        cA[mt] = c_s[mblk + mt * 16 + g4];
        cB[mt] = c_s[mblk + mt * 16 + g4 + 8];
        negA[mt] = pkf(-cA[mt] * L2E, -cA[mt] * L2E);
        negB[mt] = pkf(-cB[mt] * L2E, -cB[mt] * L2E);
        clA[mt] = cA[mt] - 80.0f;
        clB[mt] = cB[mt] - 80.0f;
    }
    u64_t sumA2[2] = {0, 0}, sumB2[2] = {0, 0};

    const size_t orow0 = (size_t)(b * N_ + r0 + mblk + g4) * N_;

    for (int t = 0; t < NTILES; t++) {
        // ---- prefetch next B tile (fp32) into regs ----
        float4 pf[8];
        if (t + 1 < NTILES) {
            const float* src = Xb + (size_t)(t + 1) * TN * D_;
            #pragma unroll
            for (int i = 0; i < 8; i++) {
                int v = tid + i * 256;
                pf[i] = *(const float4*)(src + (size_t)(v >> 4) * D_ + ((v & 15) << 2));
            }
        }

        // ---- MMA on buffer t&1 ----
        const uint32_t bsm = sbase + ((t & 1) ? B1_OFF : B0_OFF);
        const uint32_t b_base = bsm + (uint32_t)(nblk + rowoff) * LDST + kch8 * 2;

        float acc[2][8][4];
        #pragma unroll
        for (int mt = 0; mt < 2; mt++)
            #pragma unroll
            for (int nt = 0; nt < 8; nt++)
                #pragma unroll
                for (int e = 0; e < 4; e++) acc[mt][nt][e] = 0.f;

        #pragma unroll
        for (int s = 0; s < 12; s++) {
            const int ao = A_KOFF[s] * 2;
            const int bo = B_KOFF[s] * 2;
            uint32_t a0[4], a1[4];
            ldsm_x4(a_base0 + ao, a0);
            ldsm_x4(a_base1 + ao, a1);
            uint32_t bb[4][4];
            #pragma unroll
            for (int p = 0; p < 4; p++)
                ldsm_x4(b_base + (uint32_t)(p * 16) * LDST + bo, bb[p]);
            #pragma unroll
            for (int p = 0; p < 4; p++) {
                mma16816(acc[0][2*p],   a0, bb[p][0], bb[p][2]);
                mma16816(acc[0][2*p+1], a0, bb[p][1], bb[p][3]);
                mma16816(acc[1][2*p],   a1, bb[p][0], bb[p][2]);
                mma16816(acc[1][2*p+1], a1, bb[p][1], bb[p][3]);
            }
        }

        // ---- convert prefetched data, store to other buffer ----
        if (t + 1 < NTILES) {
            char* dst = sm + (((t + 1) & 1) ? B1_OFF : B0_OFF);
            #pragma unroll
            for (int i = 0; i < 8; i++) {
                int v = tid + i * 256;
                store_hilo(dst, v >> 4, (v & 15) << 2, pf[i]);
            }
        }

        // ---- epilogue: exp, row sums, store ----
        {
            const int colbase = t * TN + nblk + col2;
            #pragma unroll
            for (int mt = 0; mt < 2; mt++) {
                float* oa = out + orow0 + (size_t)(mt * 16) * N_ + colbase;
                float* ob = oa + (size_t)8 * N_;
                #pragma unroll
                for (int nt = 0; nt < 8; nt++) {
                    u64_t ea = exp_pair(acc[mt][nt][0], acc[mt][nt][1], negA[mt], clA[mt], K);
                    u64_t eb = exp_pair(acc[mt][nt][2], acc[mt][nt][3], negB[mt], clB[mt], K);
                    sumA2[mt] = f2add(sumA2[mt], ea);
                    sumB2[mt] = f2add(sumB2[mt], eb);
                    *(u64_t*)(oa + nt * 8) = ea;
                    *(u64_t*)(ob + nt * 8) = eb;
                }
            }
        }
        __syncthreads();
    }

    // ---- row-sum reduction ----
    #pragma unroll
    for (int mt = 0; mt < 2; mt++) {
        float sa0, sa1, sb0, sb1;
        upkf(sumA2[mt], sa0, sa1);
        upkf(sumB2[mt], sb0, sb1);
        float sA = sa0 + sa1, sB = sb0 + sb1;
        sA += __shfl_xor_sync(0xffffffffu, sA, 1);
        sA += __shfl_xor_sync(0xffffffffu, sA, 2);
        sB += __shfl_xor_sync(0xffffffffu, sB, 1);
        sB += __shfl_xor_sync(0xffffffffu, sB, 2);
        if ((lane & 3) == 0) {
            rsum[nhalf * 128 + mblk + mt * 16 + g4]     = sA;
            rsum[nhalf * 128 + mblk + mt * 16 + g4 + 8] = sB;
        }
    }
    __syncthreads();
    if (tid < TM) zinv[tid] = 1.0f / (rsum[tid] + rsum[128 + tid]);
    __syncthreads();

    // ---- in-place scale pass ----
    for (int r = 0; r < TM; r++) {
        float zi = zinv[r];
        float4* row = (float4*)(out + ((size_t)(b * N_ + r0 + r)) * N_);
        #pragma unroll 4
        for (int c4 = tid; c4 < N_ / 4; c4 += 256) {
            float4 v = row[c4];
            v.x *= zi; v.y *= zi; v.z *= zi; v.w *= zi;
            row[c4] = v;
        }
    }
}

extern "C" void kernel_launch(void* const* d_in, const int* in_sizes, int n_in,
                              void* d_out, int out_size) {
    const float* X = (const float*)d_in[0];
    float* out = (float*)d_out;
    cudaFuncSetAttribute(graphconstruct_mma_kernel,
                         cudaFuncAttributeMaxDynamicSharedMemorySize, SMEM_BYTES);
    graphconstruct_mma_kernel<<<B_ * (N_ / TM), 256, SMEM_BYTES>>>(X, out);
}